// round 16
// baseline (speedup 1.0000x reference)
#include <cuda_runtime.h>
#include <cuda_fp16.h>
#include <math.h>
#include <stdint.h>

#define B_    2
#define NQ    1024
#define NK    2048
#define DIM_  512
#define HID_  512
#define H_    8
#define HD_   64
#define RBH   64
#define LUT_N 2048
#define LUT_OFF 4
#define LUT_D (LUT_N - 2 * LUT_OFF - 1)   // 2039
#define LOG2E 1.4426950408889634f
#define QSC   (0.125f * LOG2E)

// fp16 tensors
__device__ __half g_Qh[(size_t)B_ * NQ * HID_];     // pre-scaled by QSC
__device__ __half g_Kh[(size_t)B_ * NK * HID_];
__device__ __half g_Vh[(size_t)B_ * H_ * HD_ * NK]; // TRANSPOSED [b][h][d][key]
__device__ __half g_attnh[(size_t)B_ * NQ * HID_];  // merged attention out
// fp32 partials + softmax denoms
__device__ float g_attn[(size_t)B_ * NQ * HID_];
__device__ float g_O2[(size_t)B_ * NQ * HID_];
__device__ float g_l[2 * B_ * H_ * NQ];
// bias machinery
__device__ float g_lut[H_ * LUT_N];                 // bias(d^2) * log2e, index-offset +4
__device__ float4 g_ext[B_ * NK];                   // tf32-pattern d^2 operand
__device__ unsigned int g_maxbits[2] = {0u, 0u};
__device__ float g_inv_step2;
// fp16 copies of harness inputs
__device__ __half g_QinH[(size_t)B_ * NQ * DIM_];
__device__ __half g_KvH[(size_t)B_ * NK * DIM_];
__device__ __half g_WqH[DIM_ * HID_];
__device__ __half g_WkH[DIM_ * HID_];
__device__ __half g_WvH[DIM_ * HID_];
__device__ __half g_WoH[HID_ * DIM_];

// ---------------------------------------------------------------------------
__device__ __forceinline__ uint32_t f2tf(float x) {
    uint32_t r; asm("cvt.rna.tf32.f32 %0, %1;" : "=r"(r) : "f"(x)); return r;
}
__device__ __forceinline__ uint32_t pk2h(float lo, float hi) {
    uint32_t r; asm("cvt.rn.f16x2.f32 %0, %1, %2;" : "=r"(r) : "f"(hi), "f"(lo)); return r;
}
__device__ __forceinline__ float ex2(float x) {
    float y; asm("ex2.approx.f32 %0, %1;" : "=f"(y) : "f"(x)); return y;
}
__device__ __forceinline__ void mma16(float* d, const uint32_t* a, uint32_t b0, uint32_t b1) {
    asm("mma.sync.aligned.m16n8k16.row.col.f32.f16.f16.f32 "
        "{%0,%1,%2,%3}, {%4,%5,%6,%7}, {%8,%9}, {%0,%1,%2,%3};"
        : "+f"(d[0]), "+f"(d[1]), "+f"(d[2]), "+f"(d[3])
        : "r"(a[0]), "r"(a[1]), "r"(a[2]), "r"(a[3]), "r"(b0), "r"(b1));
}
__device__ __forceinline__ void mma8t(float* d, const uint32_t* a, uint32_t b0) {
    asm("mma.sync.aligned.m16n8k8.row.col.f32.tf32.tf32.f32 "
        "{%0,%1,%2,%3}, {%4,%5,%6,%7}, {%8,%9}, {%0,%1,%2,%3};"
        : "+f"(d[0]), "+f"(d[1]), "+f"(d[2]), "+f"(d[3])
        : "r"(a[0]), "r"(a[1]), "r"(a[2]), "r"(a[3]), "r"(b0), "r"(0u));
}
__device__ __forceinline__ void ldsm4(uint32_t* r, uint32_t saddr) {
    asm volatile("ldmatrix.sync.aligned.m8n8.x4.shared.b16 {%0,%1,%2,%3}, [%4];"
        : "=r"(r[0]), "=r"(r[1]), "=r"(r[2]), "=r"(r[3]) : "r"(saddr));
}
__device__ __forceinline__ void ldsm4t(uint32_t* r, uint32_t saddr) {
    asm volatile("ldmatrix.sync.aligned.m8n8.x4.trans.shared.b16 {%0,%1,%2,%3}, [%4];"
        : "=r"(r[0]), "=r"(r[1]), "=r"(r[2]), "=r"(r[3]) : "r"(saddr));
}
__device__ __forceinline__ void cpa16(uint32_t s, const void* g) {
    asm volatile("cp.async.cg.shared.global [%0], [%1], 16;" :: "r"(s), "l"(g));
}
__device__ __forceinline__ uint32_t s2u(const void* p) {
    return (uint32_t)__cvta_generic_to_shared(p);
}

// ---------------------------------------------------------------------------
// conv: fp32 -> fp16 for all matmul operands + coord-norm max
// ---------------------------------------------------------------------------
__global__ __launch_bounds__(256) void conv_kernel(
    const float4* __restrict__ qin, const float4* __restrict__ kvin,
    const float4* __restrict__ wq, const float4* __restrict__ wk,
    const float4* __restrict__ wv, const float4* __restrict__ wo,
    const float* __restrict__ qc, const float* __restrict__ kc)
{
    int i = blockIdx.x * 256 + threadIdx.x;
    float4 v; __half* dst;
    if      (i < 262144) { v = qin[i];            dst = g_QinH + (size_t)i * 4; }
    else if (i < 786432) { v = kvin[i - 262144];  dst = g_KvH + (size_t)(i - 262144) * 4; }
    else if (i < 851968) { v = wq[i - 786432];    dst = g_WqH + (size_t)(i - 786432) * 4; }
    else if (i < 917504) { v = wk[i - 851968];    dst = g_WkH + (size_t)(i - 851968) * 4; }
    else if (i < 983040) { v = wv[i - 917504];    dst = g_WvH + (size_t)(i - 917504) * 4; }
    else                 { v = wo[i - 983040];    dst = g_WoH + (size_t)(i - 983040) * 4; }
    *(uint2*)dst = make_uint2(pk2h(v.x, v.y), pk2h(v.z, v.w));

    const int NQT = B_ * NQ, NKT = B_ * NK;
    if (i < NQT + NKT) {
        float n; int which;
        if (i < NQT) {
            float x = qc[i*3], y = qc[i*3+1], z = qc[i*3+2];
            n = sqrtf(fmaf(x,x,fmaf(y,y,z*z))); which = 0;
        } else {
            int j = i - NQT;
            float x = kc[j*3], y = kc[j*3+1], z = kc[j*3+2];
            n = sqrtf(fmaf(x,x,fmaf(y,y,z*z))); which = 1;
        }
        atomicMax(&g_maxbits[which], __float_as_uint(n));
    }
}

// ---------------------------------------------------------------------------
// lut_kernel: blocks 0-7 per-head LUT (2048, +4 guard offset); 8-23 ext table
// ---------------------------------------------------------------------------
__global__ __launch_bounds__(256) void lut_kernel(
    const float* __restrict__ W1, const float* __restrict__ b1,
    const float* __restrict__ W2, const float* __restrict__ b2,
    const float* __restrict__ kc)
{
    const int blk = blockIdx.x;
    const int t = threadIdx.x;
    const float dmax = __uint_as_float(g_maxbits[0]) + __uint_as_float(g_maxbits[1]) + 1e-3f;
    const float step2 = dmax * dmax / (float)LUT_D;
    const float is2 = 1.0f / step2;

    if (blk >= 8) {
        const int j = (blk - 8) * 256 + t;
        const float* p = kc + (size_t)j * 3;
        const float x = p[0], y = p[1], z = p[2];
        float4 e;
        e.x = __uint_as_float(f2tf(-2.f * x * is2));
        e.y = __uint_as_float(f2tf(-2.f * y * is2));
        e.z = __uint_as_float(f2tf(-2.f * z * is2));
        e.w = __uint_as_float(f2tf(fmaf(x, x, fmaf(y, y, z * z)) * is2));
        g_ext[j] = e;
        return;
    }

    __shared__ float sW1[RBH], sb1[RBH], sW2[RBH * H_];
    if (t < RBH) { sW1[t] = W1[t]; sb1[t] = b1[t]; }
    for (int i = t; i < RBH * H_; i += 256) sW2[i] = W2[i];
    __syncthreads();

    if (blk == 0 && t == 0) g_inv_step2 = is2;

    int i = blk * 256 + t;
    int j = min(max(i - LUT_OFF, 0), LUT_D);   // guard entries on both ends
    float d = sqrtf(step2 * (float)j);

    float o[H_];
    #pragma unroll
    for (int hh = 0; hh < H_; hh++) o[hh] = b2[hh];
    #pragma unroll 8
    for (int jj = 0; jj < RBH; jj++) {
        float x = fmaf(d, sW1[jj], sb1[jj]);
        float s = __fdividef(x, 1.0f + __expf(-x));
        #pragma unroll
        for (int hh = 0; hh < H_; hh++)
            o[hh] = fmaf(s, sW2[jj * H_ + hh], o[hh]);
    }
    #pragma unroll
    for (int hh = 0; hh < H_; hh++)
        g_lut[hh * LUT_N + i] = o[hh] * LOG2E;
}

// ---------------------------------------------------------------------------
// fp16 GEMM body (unchanged): BMxBN, BK=32, 3-stage cp.async, LDSM.
// mode: 0 fp32 store, 1 fp16, 2 fp16*QSC, 3 fp16 transposed V store.
// ---------------------------------------------------------------------------
#define GASTR 40   // halves

template<int BM, int BN>
__device__ __forceinline__ void gemm_h_body(
    const __half* __restrict__ A, const __half* __restrict__ Bm,
    void* __restrict__ Cp, int N, int K, int row0, int mode, char* sm)
{
    constexpr int BSTR = BN + 8;
    constexpr int ASZ = BM * GASTR * 2;
    constexpr int BSZ = 32 * BSTR * 2;
    constexpr int MF  = BM / 64;
    constexpr int NFW = BN / 16;
    char* As = sm;
    char* Bs = sm + 3 * ASZ;

    const int tid = threadIdx.x;
    const int lane = tid & 31, wid = tid >> 5;
    const int wm = (wid >> 1) * (BM / 4), wn = (wid & 1) * (BN / 2);
    const int col0 = blockIdx.x * BN;
    const int lq = lane >> 2, lr = lane & 3;

    const int ar = (BM == 128) ? (tid >> 1) : (tid >> 2);
    const int ac = (BM == 128) ? ((tid & 1) * 16) : ((tid & 3) * 8);
    const int bk = tid >> 3;
    const int bn = (tid & 7) * ((BN == 128) ? 16 : 8);

    float acc[MF][NFW][4] = {};

    auto issue = [&](int k0) {
        const int st = (k0 >> 5) % 3;
        uint32_t a_s = s2u(As + st * ASZ + (ar * GASTR + ac) * 2);
        const __half* ag = A + (size_t)(row0 + ar) * K + k0 + ac;
        cpa16(a_s, ag);
        if (BM == 128) cpa16(a_s + 16, ag + 8);
        uint32_t b_s = s2u(Bs + st * BSZ + (bk * BSTR + bn) * 2);
        const __half* bg = Bm + (size_t)(k0 + bk) * N + col0 + bn;
        cpa16(b_s, bg);
        if (BN == 128) cpa16(b_s + 16, bg + 8);
        asm volatile("cp.async.commit_group;" ::: "memory");
    };

    issue(0); issue(32);

    const int a_lane = (lane & 15) * (GASTR * 2) + (lane >> 4) * 16;
    const int b_lane = ((lane & 7) + ((lane >> 3) & 1) * 8) * (BSTR * 2) + (lane >> 4) * 16;

    for (int k0 = 0; k0 < K; k0 += 32) {
        if (k0 + 64 < K) {
            asm volatile("cp.async.wait_group 1;" ::: "memory");
            __syncthreads();
            issue(k0 + 64);
        } else if (k0 + 32 < K) {
            asm volatile("cp.async.wait_group 1;" ::: "memory");
            __syncthreads();
        } else {
            asm volatile("cp.async.wait_group 0;" ::: "memory");
            __syncthreads();
        }
        const int st = (k0 >> 5) % 3;
        const uint32_t a_b = s2u(As + st * ASZ);
        const uint32_t b_b = s2u(Bs + st * BSZ);

        #pragma unroll
        for (int ks = 0; ks < 2; ks++) {
            uint32_t af[MF][4], bf[NFW / 2][4];
            #pragma unroll
            for (int mf = 0; mf < MF; mf++)
                ldsm4(af[mf], a_b + (wm + mf * 16) * (GASTR * 2) + ks * 32 + a_lane);
            #pragma unroll
            for (int n2 = 0; n2 < NFW / 2; n2++)
                ldsm4t(bf[n2], b_b + ks * 16 * (BSTR * 2) + (wn + n2 * 16) * 2 + b_lane);
            #pragma unroll
            for (int mf = 0; mf < MF; mf++)
                #pragma unroll
                for (int nf = 0; nf < NFW; nf++)
                    mma16(acc[mf][nf], af[mf], bf[nf >> 1][(nf & 1) * 2],
                          bf[nf >> 1][(nf & 1) * 2 + 1]);
        }
        __syncthreads();
    }

    #pragma unroll
    for (int mf = 0; mf < MF; mf++)
        #pragma unroll
        for (int nf = 0; nf < NFW; nf++) {
            const int r = row0 + wm + mf * 16 + lq;
            const int c = col0 + wn + nf * 8 + 2 * lr;
            float* v = acc[mf][nf];
            if (mode == 0) {
                float* C = (float*)Cp;
                *(float2*)&C[(size_t)r * N + c]       = make_float2(v[0], v[1]);
                *(float2*)&C[(size_t)(r + 8) * N + c] = make_float2(v[2], v[3]);
            } else if (mode == 3) {
                __half* C = (__half*)Cp;
                #pragma unroll
                for (int rw = 0; rw < 2; rw++) {
                    const int rr = r + rw * 8;
                    const int bb = rr >> 11, key = rr & 2047;
                    #pragma unroll
                    for (int cc = 0; cc < 2; cc++) {
                        const int col = c + cc;
                        C[(((size_t)bb * H_ + (col >> 6)) * HD_ + (col & 63)) * NK + key]
                            = __float2half_rn(v[rw * 2 + cc]);
                    }
                }
            } else {
                const float s = (mode == 2) ? QSC : 1.0f;
                __half* C = (__half*)Cp;
                *(uint32_t*)&C[(size_t)r * N + c]       = pk2h(v[0] * s, v[1] * s);
                *(uint32_t*)&C[(size_t)(r + 8) * N + c] = pk2h(v[2] * s, v[3] * s);
            }
        }
}

#define QKV_SMEM (3 * (128 * GASTR * 2 + 32 * 136 * 2))
#define OUT_SMEM (3 * (64 * GASTR * 2 + 32 * 72 * 2))

__global__ __launch_bounds__(256, 2) void gemm_qkv_kernel()
{
    extern __shared__ char gsm[];
    int by = blockIdx.y;
    const __half *A, *Bw; void* C; int mode;
    if (by < 16)      { A = g_QinH; Bw = g_WqH; C = g_Qh; mode = 2; }
    else if (by < 48) { A = g_KvH;  Bw = g_WkH; C = g_Kh; mode = 1; by -= 16; }
    else              { A = g_KvH;  Bw = g_WvH; C = g_Vh; mode = 3; by -= 48; }
    gemm_h_body<128, 128>(A, Bw, C, HID_, DIM_, by * 128, mode, gsm);
}

__global__ __launch_bounds__(256, 3) void gemm_out_kernel(float* __restrict__ out)
{
    extern __shared__ char gsm[];
    gemm_h_body<64, 64>(g_attnh, g_WoH, out, DIM_, HID_, blockIdx.y * 64, 0, gsm);
}

// ---------------------------------------------------------------------------
// fp16 flash attention: CTA split-K(2), no-max softmax, register-resident P,
// clamp-free nearest LUT, 64-key tiles, 2-stage cp.async double buffer.
// 64 q x 1024 keys, 128 thr / 4 warps, 4 CTAs/SM.
// ---------------------------------------------------------------------------
#define AKT    64
#define KSTRH  72    // K tile halves/row (144B rows, phase 4r: conflict-free)
#define VSTRH  72    // V^T tile halves/row (64 keys)
#define KB_    (AKT * KSTRH * 2)          // 9216
#define EB_    1024                       // 64 keys * 16B
#define VB_    (HD_ * VSTRH * 2)          // 9216
#define STGB   (KB_ + EB_ + VB_)          // 19456 per stage
#define OFF_LUT (2 * STGB)                // 38912; 2048 fp32 = 8192 B
#define ATT_SMEM_BYTES (2 * STGB + 8192)  // 47104

__global__ __launch_bounds__(128, 4) void attn_kernel(const float* __restrict__ qc)
{
    extern __shared__ char smc[];
    float* slut = (float*)(smc + OFF_LUT);

    const int b   = blockIdx.z >> 1;
    const int ks_ = blockIdx.z & 1;
    const int h   = blockIdx.y;
    const int q0  = blockIdx.x * 64;
    const int tid = threadIdx.x;
    const int lane = tid & 31;
    const int w    = tid >> 5;
    const int lq   = lane >> 2;
    const int lr   = lane & 3;
    const int kstart = ks_ * (NK / 2);

    {   // stage fp32 LUT
        const float* lb = g_lut + h * LUT_N;
        for (int i = tid; i < LUT_N; i += 128) slut[i] = lb[i];
    }
    const float inv_step2 = g_inv_step2;

    // ldsm lane offsets (bytes); K and V^T share stride 72
    const int m_lane = (lane & 7) * (KSTRH * 2) + (lane >> 3) * 16;
    const int e_lane = lane * 16;

    // Q fragments
    uint32_t qa[4][4], qa2[4];
    float qn2s0, qn2s1;
    {
        const size_t r0 = ((size_t)(b * NQ + q0 + w * 16 + lq)) * HID_ + h * HD_;
        const size_t r1 = r0 + 8 * HID_;
        #pragma unroll
        for (int ks = 0; ks < 4; ks++) {
            qa[ks][0] = *(const uint32_t*)&g_Qh[r0 + ks * 16 + 2 * lr];
            qa[ks][1] = *(const uint32_t*)&g_Qh[r1 + ks * 16 + 2 * lr];
            qa[ks][2] = *(const uint32_t*)&g_Qh[r0 + ks * 16 + 2 * lr + 8];
            qa[ks][3] = *(const uint32_t*)&g_Qh[r1 + ks * 16 + 2 * lr + 8];
        }
        const float* p0 = qc + ((size_t)b * NQ + q0 + w * 16 + lq) * 3;
        const float* p1 = p0 + 8 * 3;
        float c0[4] = {p0[0], p0[1], p0[2], 1.0f};
        float c1[4] = {p1[0], p1[1], p1[2], 1.0f};
        qa2[0] = f2tf(c0[lr]);
        qa2[1] = f2tf(c1[lr]);
        qa2[2] = 0u; qa2[3] = 0u;
        // +LUT_OFF guard folded into the accumulator init
        qn2s0 = fmaf(c0[0], c0[0], fmaf(c0[1], c0[1], c0[2] * c0[2])) * inv_step2
              + (float)LUT_OFF;
        qn2s1 = fmaf(c1[0], c1[0], fmaf(c1[1], c1[1], c1[2] * c1[2])) * inv_step2
              + (float)LUT_OFF;
    }

    float of[8][4] = {};
    float l0 = 0.f, l1 = 0.f;

    const __half* Kp  = g_Kh + ((size_t)b * NK) * HID_ + h * HD_;
    const __half* Vpt = g_Vh + ((size_t)(b * H_ + h) * HD_) * NK;

    const int lrow = tid >> 1;            // loader row (key for K, d for V)
    const int lcol = (tid & 1) * 32;      // halves

    auto issue = [&](int t) {
        char* stg = smc + (t & 1) * STGB;
        const __half* kg = Kp + (size_t)(kstart + t * AKT + lrow) * HID_ + lcol;
        uint32_t kd = s2u(stg + (lrow * KSTRH + lcol) * 2);
        cpa16(kd, kg); cpa16(kd + 16, kg + 8);
        cpa16(kd + 32, kg + 16); cpa16(kd + 48, kg + 24);
        if (tid < AKT)
            cpa16(s2u(stg + KB_ + tid * 16),
                  g_ext + (size_t)b * NK + kstart + t * AKT + tid);
        const __half* vg = Vpt + (size_t)lrow * NK + kstart + t * AKT + lcol;
        uint32_t vd = s2u(stg + KB_ + EB_ + (lrow * VSTRH + lcol) * 2);
        cpa16(vd, vg); cpa16(vd + 16, vg + 8);
        cpa16(vd + 32, vg + 16); cpa16(vd + 48, vg + 24);
        asm volatile("cp.async.commit_group;" ::: "memory");
    };

    const int NT = (NK / 2) / AKT;   // 16
    issue(0);

    for (int t = 0; t < NT; t++) {
        if (t + 1 < NT) {
            issue(t + 1);
            asm volatile("cp.async.wait_group 1;" ::: "memory");
        } else {
            asm volatile("cp.async.wait_group 0;" ::: "memory");
        }
        __syncthreads();

        char* stg = smc + (t & 1) * STGB;
        const uint32_t kb_s = s2u(stg);
        const uint32_t eb_s = s2u(stg + KB_);
        const uint32_t vb_s = s2u(stg + KB_ + EB_);

        // ---- QK^T ----
        float sacc[8][4] = {};
        #pragma unroll
        for (int nf = 0; nf < 8; nf++) {
            const uint32_t kbase = kb_s + nf * 8 * (KSTRH * 2) + m_lane;
            uint32_t kb[4];
            ldsm4(kb, kbase);
            mma16(sacc[nf], qa[0], kb[0], kb[1]);
            mma16(sacc[nf], qa[1], kb[2], kb[3]);
            ldsm4(kb, kbase + 64);
            mma16(sacc[nf], qa[2], kb[0], kb[1]);
            mma16(sacc[nf], qa[3], kb[2], kb[3]);
        }

        // ---- d^2 ext fragments (2 LDSM cover 64 keys) ----
        uint32_t eb[8];
        ldsm4(eb,     eb_s + e_lane);
        ldsm4(eb + 4, eb_s + 512 + e_lane);

        // ---- bias (clamp-free nearest LUT) + no-max softmax; P -> A-frags ----
        uint32_t pa[4][4];
        float ps0 = 0.f, ps1 = 0.f;
        #pragma unroll
        for (int nf = 0; nf < 8; nf++) {
            float dd4[4] = {qn2s0, qn2s0, qn2s1, qn2s1};
            mma8t(dd4, qa2, eb[nf]);
            float p4[4];
            #pragma unroll
            for (int j = 0; j < 4; j++)
                p4[j] = ex2(sacc[nf][j] + slut[__float2int_rn(dd4[j])]);
            ps0 += p4[0] + p4[1];
            ps1 += p4[2] + p4[3];
            pa[nf >> 1][(nf & 1) * 2]     = pk2h(p4[0], p4[1]);
            pa[nf >> 1][(nf & 1) * 2 + 1] = pk2h(p4[2], p4[3]);
        }
        l0 += ps0;
        l1 += ps1;

        // ---- P V (P in registers, V via LDSM) ----
        #pragma unroll
        for (int nf = 0; nf < 8; nf++) {
            const uint32_t vbase = vb_s + nf * 8 * (VSTRH * 2) + m_lane;
            uint32_t vb[4];
            ldsm4(vb, vbase);
            mma16(of[nf], pa[0], vb[0], vb[1]);
            mma16(of[nf], pa[1], vb[2], vb[3]);
            ldsm4(vb, vbase + 64);
            mma16(of[nf], pa[2], vb[0], vb[1]);
            mma16(of[nf], pa[3], vb[2], vb[3]);
        }

        __syncthreads();
    }

    // epilogue: unnormalized fp32 partial + l
    float* pO = ks_ ? g_O2 : g_attn;
    const size_t r0 = ((size_t)(b * NQ + q0 + w * 16 + lq)) * HID_ + h * HD_;
    const size_t r1 = r0 + 8 * HID_;
    #pragma unroll
    for (int nf = 0; nf < 8; nf++) {
        const int c = nf * 8 + 2 * lr;
        *(float2*)&pO[r0 + c] = make_float2(of[nf][0], of[nf][1]);
        *(float2*)&pO[r1 + c] = make_float2(of[nf][2], of[nf][3]);
    }
    l0 += __shfl_xor_sync(0xffffffffu, l0, 1);
    l0 += __shfl_xor_sync(0xffffffffu, l0, 2);
    l1 += __shfl_xor_sync(0xffffffffu, l1, 1);
    l1 += __shfl_xor_sync(0xffffffffu, l1, 2);
    if (lr == 0) {
        const size_t base = (((size_t)ks_ * B_ + b) * H_ + h) * NQ;
        const int qr = q0 + w * 16 + lq;
        g_l[base + qr]     = l0;
        g_l[base + qr + 8] = l1;
    }
}

// ---------------------------------------------------------------------------
__global__ __launch_bounds__(512) void merge_kernel()
{
    const int row = blockIdx.x;
    const int b = row >> 10;
    const int q = row & 1023;
    const int c = threadIdx.x;
    const int h = c >> 6;

    const float lA = g_l[(((size_t)0 * B_ + b) * H_ + h) * NQ + q];
    const float lB = g_l[(((size_t)1 * B_ + b) * H_ + h) * NQ + q];
    const float inv = __fdividef(1.f, lA + lB);

    const size_t o = (size_t)row * HID_ + c;
    g_attnh[o] = __float2half_rn((g_attn[o] + g_O2[o]) * inv);
}

// ---------------------------------------------------------------------------
extern "C" void kernel_launch(void* const* d_in, const int* in_sizes, int n_in,
                              void* d_out, int out_size)
{
    const float* q_in      = (const float*)d_in[0];
    const float* kv_in     = (const float*)d_in[1];
    const float* q_coords  = (const float*)d_in[2];
    const float* kv_coords = (const float*)d_in[3];
    const float* Wq        = (const float*)d_in[4];
    const float* Wk        = (const float*)d_in[5];
    const float* Wv        = (const float*)d_in[6];
    const float* Wo        = (const float*)d_in[7];
    const float* W1        = (const float*)d_in[8];
    const float* b1        = (const float*)d_in[9];
    const float* W2        = (const float*)d_in[10];
    const float* b2        = (const float*)d_in[11];
    float* out             = (float*)d_out;

    static bool attr_set = false;
    if (!attr_set) {
        cudaFuncSetAttribute(attn_kernel,
            cudaFuncAttributeMaxDynamicSharedMemorySize, ATT_SMEM_BYTES);
        cudaFuncSetAttribute(gemm_qkv_kernel,
            cudaFuncAttributeMaxDynamicSharedMemorySize, QKV_SMEM);
        cudaFuncSetAttribute(gemm_out_kernel,
            cudaFuncAttributeMaxDynamicSharedMemorySize, OUT_SMEM);
        attr_set = true;
    }

    conv_kernel<<<4096, 256>>>((const float4*)q_in, (const float4*)kv_in,
                               (const float4*)Wq, (const float4*)Wk,
                               (const float4*)Wv, (const float4*)Wo,
                               q_coords, kv_coords);
    lut_kernel<<<24, 256>>>(W1, b1, W2, b2, kv_coords);

    gemm_qkv_kernel<<<dim3(HID_ / 128, 80), 256, QKV_SMEM>>>();

    attn_kernel<<<dim3(NQ / 64, H_, B_ * 2), 128, ATT_SMEM_BYTES>>>(q_coords);

    merge_kernel<<<B_ * NQ, 512>>>();

    gemm_out_kernel<<<dim3(DIM_ / 64, (B_ * NQ) / 64), 256, OUT_SMEM>>>(out);
}

// round 17
// speedup vs baseline: 1.1092x; 1.1092x over previous
#include <cuda_runtime.h>
#include <cuda_fp16.h>
#include <math.h>
#include <stdint.h>

#define B_    2
#define NQ    1024
#define NK    2048
#define DIM_  512
#define HID_  512
#define H_    8
#define HD_   64
#define RBH   64
#define LUT_N 2048
#define LUT_OFF 4
#define LUT_D (LUT_N - 2 * LUT_OFF - 1)   // 2039
#define LOG2E 1.4426950408889634f
#define QSC   (0.125f * LOG2E)

// fp16 tensors
__device__ __half g_Qh[(size_t)B_ * NQ * HID_];     // pre-scaled by QSC
__device__ __half g_Kh[(size_t)B_ * NK * HID_];
__device__ __half g_Vh[(size_t)B_ * H_ * HD_ * NK]; // TRANSPOSED [b][h][d][key]
__device__ __half g_attnh[(size_t)B_ * NQ * HID_];  // merged attention out
// fp32 partials + softmax denoms
__device__ float g_attn[(size_t)B_ * NQ * HID_];
__device__ float g_O2[(size_t)B_ * NQ * HID_];
__device__ float g_l[2 * B_ * H_ * NQ];
// bias machinery
__device__ float g_lut[H_ * LUT_N];                 // bias(d^2) * log2e, +4 guard offset
__device__ float4 g_ext[B_ * NK];                   // tf32-pattern d^2 operand
__device__ unsigned int g_maxbits[2] = {0u, 0u};
__device__ float g_inv_step2;
// fp16 copies of harness inputs
__device__ __half g_QinH[(size_t)B_ * NQ * DIM_];
__device__ __half g_KvH[(size_t)B_ * NK * DIM_];
__device__ __half g_WqH[DIM_ * HID_];
__device__ __half g_WkH[DIM_ * HID_];
__device__ __half g_WvH[DIM_ * HID_];
__device__ __half g_WoH[HID_ * DIM_];

// ---------------------------------------------------------------------------
__device__ __forceinline__ uint32_t f2tf(float x) {
    uint32_t r; asm("cvt.rna.tf32.f32 %0, %1;" : "=r"(r) : "f"(x)); return r;
}
__device__ __forceinline__ uint32_t pk2h(float lo, float hi) {
    uint32_t r; asm("cvt.rn.f16x2.f32 %0, %1, %2;" : "=r"(r) : "f"(hi), "f"(lo)); return r;
}
__device__ __forceinline__ float ex2(float x) {
    float y; asm("ex2.approx.f32 %0, %1;" : "=f"(y) : "f"(x)); return y;
}
__device__ __forceinline__ void mma16(float* d, const uint32_t* a, uint32_t b0, uint32_t b1) {
    asm("mma.sync.aligned.m16n8k16.row.col.f32.f16.f16.f32 "
        "{%0,%1,%2,%3}, {%4,%5,%6,%7}, {%8,%9}, {%0,%1,%2,%3};"
        : "+f"(d[0]), "+f"(d[1]), "+f"(d[2]), "+f"(d[3])
        : "r"(a[0]), "r"(a[1]), "r"(a[2]), "r"(a[3]), "r"(b0), "r"(b1));
}
__device__ __forceinline__ void mma8t(float* d, const uint32_t* a, uint32_t b0) {
    asm("mma.sync.aligned.m16n8k8.row.col.f32.tf32.tf32.f32 "
        "{%0,%1,%2,%3}, {%4,%5,%6,%7}, {%8,%9}, {%0,%1,%2,%3};"
        : "+f"(d[0]), "+f"(d[1]), "+f"(d[2]), "+f"(d[3])
        : "r"(a[0]), "r"(a[1]), "r"(a[2]), "r"(a[3]), "r"(b0), "r"(0u));
}
__device__ __forceinline__ void ldsm4(uint32_t* r, uint32_t saddr) {
    asm volatile("ldmatrix.sync.aligned.m8n8.x4.shared.b16 {%0,%1,%2,%3}, [%4];"
        : "=r"(r[0]), "=r"(r[1]), "=r"(r[2]), "=r"(r[3]) : "r"(saddr));
}
__device__ __forceinline__ void ldsm4t(uint32_t* r, uint32_t saddr) {
    asm volatile("ldmatrix.sync.aligned.m8n8.x4.trans.shared.b16 {%0,%1,%2,%3}, [%4];"
        : "=r"(r[0]), "=r"(r[1]), "=r"(r[2]), "=r"(r[3]) : "r"(saddr));
}
__device__ __forceinline__ void cpa16(uint32_t s, const void* g) {
    asm volatile("cp.async.cg.shared.global [%0], [%1], 16;" :: "r"(s), "l"(g));
}
__device__ __forceinline__ uint32_t s2u(const void* p) {
    return (uint32_t)__cvta_generic_to_shared(p);
}

// ---------------------------------------------------------------------------
// conv: fp32 -> fp16 for all matmul operands + coord-norm max
// ---------------------------------------------------------------------------
__global__ __launch_bounds__(256) void conv_kernel(
    const float4* __restrict__ qin, const float4* __restrict__ kvin,
    const float4* __restrict__ wq, const float4* __restrict__ wk,
    const float4* __restrict__ wv, const float4* __restrict__ wo,
    const float* __restrict__ qc, const float* __restrict__ kc)
{
    int i = blockIdx.x * 256 + threadIdx.x;
    float4 v; __half* dst;
    if      (i < 262144) { v = qin[i];            dst = g_QinH + (size_t)i * 4; }
    else if (i < 786432) { v = kvin[i - 262144];  dst = g_KvH + (size_t)(i - 262144) * 4; }
    else if (i < 851968) { v = wq[i - 786432];    dst = g_WqH + (size_t)(i - 786432) * 4; }
    else if (i < 917504) { v = wk[i - 851968];    dst = g_WkH + (size_t)(i - 851968) * 4; }
    else if (i < 983040) { v = wv[i - 917504];    dst = g_WvH + (size_t)(i - 917504) * 4; }
    else                 { v = wo[i - 983040];    dst = g_WoH + (size_t)(i - 983040) * 4; }
    *(uint2*)dst = make_uint2(pk2h(v.x, v.y), pk2h(v.z, v.w));

    const int NQT = B_ * NQ, NKT = B_ * NK;
    if (i < NQT + NKT) {
        float n; int which;
        if (i < NQT) {
            float x = qc[i*3], y = qc[i*3+1], z = qc[i*3+2];
            n = sqrtf(fmaf(x,x,fmaf(y,y,z*z))); which = 0;
        } else {
            int j = i - NQT;
            float x = kc[j*3], y = kc[j*3+1], z = kc[j*3+2];
            n = sqrtf(fmaf(x,x,fmaf(y,y,z*z))); which = 1;
        }
        atomicMax(&g_maxbits[which], __float_as_uint(n));
    }
}

// ---------------------------------------------------------------------------
// lut_kernel: blocks 0-7 per-head LUT (2048, +4 guard offset); 8-23 ext table
// ---------------------------------------------------------------------------
__global__ __launch_bounds__(256) void lut_kernel(
    const float* __restrict__ W1, const float* __restrict__ b1,
    const float* __restrict__ W2, const float* __restrict__ b2,
    const float* __restrict__ kc)
{
    const int blk = blockIdx.x;
    const int t = threadIdx.x;
    const float dmax = __uint_as_float(g_maxbits[0]) + __uint_as_float(g_maxbits[1]) + 1e-3f;
    const float step2 = dmax * dmax / (float)LUT_D;
    const float is2 = 1.0f / step2;

    if (blk >= 8) {
        const int j = (blk - 8) * 256 + t;
        const float* p = kc + (size_t)j * 3;
        const float x = p[0], y = p[1], z = p[2];
        float4 e;
        e.x = __uint_as_float(f2tf(-2.f * x * is2));
        e.y = __uint_as_float(f2tf(-2.f * y * is2));
        e.z = __uint_as_float(f2tf(-2.f * z * is2));
        e.w = __uint_as_float(f2tf(fmaf(x, x, fmaf(y, y, z * z)) * is2));
        g_ext[j] = e;
        return;
    }

    __shared__ float sW1[RBH], sb1[RBH], sW2[RBH * H_];
    if (t < RBH) { sW1[t] = W1[t]; sb1[t] = b1[t]; }
    for (int i = t; i < RBH * H_; i += 256) sW2[i] = W2[i];
    __syncthreads();

    if (blk == 0 && t == 0) g_inv_step2 = is2;

    int i = blk * 256 + t;
    int j = min(max(i - LUT_OFF, 0), LUT_D);   // guard entries
    float d = sqrtf(step2 * (float)j);

    float o[H_];
    #pragma unroll
    for (int hh = 0; hh < H_; hh++) o[hh] = b2[hh];
    #pragma unroll 8
    for (int jj = 0; jj < RBH; jj++) {
        float x = fmaf(d, sW1[jj], sb1[jj]);
        float s = __fdividef(x, 1.0f + __expf(-x));
        #pragma unroll
        for (int hh = 0; hh < H_; hh++)
            o[hh] = fmaf(s, sW2[jj * H_ + hh], o[hh]);
    }
    #pragma unroll
    for (int hh = 0; hh < H_; hh++)
        g_lut[hh * LUT_N + i] = o[hh] * LOG2E;
}

// ---------------------------------------------------------------------------
// fp16 GEMM body: BMxBN, BK=32, 3-stage cp.async, LDSM all fragments.
// mode: 0 fp32 store, 1 fp16, 2 fp16*QSC, 3 fp16 transposed V store.
// ---------------------------------------------------------------------------
#define GASTR 40   // halves

template<int BM, int BN>
__device__ __forceinline__ void gemm_h_body(
    const __half* __restrict__ A, const __half* __restrict__ Bm,
    void* __restrict__ Cp, int N, int K, int row0, int mode, char* sm)
{
    constexpr int BSTR = BN + 8;
    constexpr int ASZ = BM * GASTR * 2;
    constexpr int BSZ = 32 * BSTR * 2;
    constexpr int MF  = BM / 64;
    constexpr int NFW = BN / 16;
    char* As = sm;
    char* Bs = sm + 3 * ASZ;

    const int tid = threadIdx.x;
    const int lane = tid & 31, wid = tid >> 5;
    const int wm = (wid >> 1) * (BM / 4), wn = (wid & 1) * (BN / 2);
    const int col0 = blockIdx.x * BN;
    const int lq = lane >> 2, lr = lane & 3;

    const int ar = (BM == 128) ? (tid >> 1) : (tid >> 2);
    const int ac = (BM == 128) ? ((tid & 1) * 16) : ((tid & 3) * 8);
    const int bk = tid >> 3;
    const int bn = (tid & 7) * ((BN == 128) ? 16 : 8);

    float acc[MF][NFW][4] = {};

    auto issue = [&](int k0) {
        const int st = (k0 >> 5) % 3;
        uint32_t a_s = s2u(As + st * ASZ + (ar * GASTR + ac) * 2);
        const __half* ag = A + (size_t)(row0 + ar) * K + k0 + ac;
        cpa16(a_s, ag);
        if (BM == 128) cpa16(a_s + 16, ag + 8);
        uint32_t b_s = s2u(Bs + st * BSZ + (bk * BSTR + bn) * 2);
        const __half* bg = Bm + (size_t)(k0 + bk) * N + col0 + bn;
        cpa16(b_s, bg);
        if (BN == 128) cpa16(b_s + 16, bg + 8);
        asm volatile("cp.async.commit_group;" ::: "memory");
    };

    issue(0); issue(32);

    const int a_lane = (lane & 15) * (GASTR * 2) + (lane >> 4) * 16;
    const int b_lane = ((lane & 7) + ((lane >> 3) & 1) * 8) * (BSTR * 2) + (lane >> 4) * 16;

    for (int k0 = 0; k0 < K; k0 += 32) {
        if (k0 + 64 < K) {
            asm volatile("cp.async.wait_group 1;" ::: "memory");
            __syncthreads();
            issue(k0 + 64);
        } else if (k0 + 32 < K) {
            asm volatile("cp.async.wait_group 1;" ::: "memory");
            __syncthreads();
        } else {
            asm volatile("cp.async.wait_group 0;" ::: "memory");
            __syncthreads();
        }
        const int st = (k0 >> 5) % 3;
        const uint32_t a_b = s2u(As + st * ASZ);
        const uint32_t b_b = s2u(Bs + st * BSZ);

        #pragma unroll
        for (int ks = 0; ks < 2; ks++) {
            uint32_t af[MF][4], bf[NFW / 2][4];
            #pragma unroll
            for (int mf = 0; mf < MF; mf++)
                ldsm4(af[mf], a_b + (wm + mf * 16) * (GASTR * 2) + ks * 32 + a_lane);
            #pragma unroll
            for (int n2 = 0; n2 < NFW / 2; n2++)
                ldsm4t(bf[n2], b_b + ks * 16 * (BSTR * 2) + (wn + n2 * 16) * 2 + b_lane);
            #pragma unroll
            for (int mf = 0; mf < MF; mf++)
                #pragma unroll
                for (int nf = 0; nf < NFW; nf++)
                    mma16(acc[mf][nf], af[mf], bf[nf >> 1][(nf & 1) * 2],
                          bf[nf >> 1][(nf & 1) * 2 + 1]);
        }
        __syncthreads();
    }

    #pragma unroll
    for (int mf = 0; mf < MF; mf++)
        #pragma unroll
        for (int nf = 0; nf < NFW; nf++) {
            const int r = row0 + wm + mf * 16 + lq;
            const int c = col0 + wn + nf * 8 + 2 * lr;
            float* v = acc[mf][nf];
            if (mode == 0) {
                float* C = (float*)Cp;
                *(float2*)&C[(size_t)r * N + c]       = make_float2(v[0], v[1]);
                *(float2*)&C[(size_t)(r + 8) * N + c] = make_float2(v[2], v[3]);
            } else if (mode == 3) {
                __half* C = (__half*)Cp;
                #pragma unroll
                for (int rw = 0; rw < 2; rw++) {
                    const int rr = r + rw * 8;
                    const int bb = rr >> 11, key = rr & 2047;
                    #pragma unroll
                    for (int cc = 0; cc < 2; cc++) {
                        const int col = c + cc;
                        C[(((size_t)bb * H_ + (col >> 6)) * HD_ + (col & 63)) * NK + key]
                            = __float2half_rn(v[rw * 2 + cc]);
                    }
                }
            } else {
                const float s = (mode == 2) ? QSC : 1.0f;
                __half* C = (__half*)Cp;
                *(uint32_t*)&C[(size_t)r * N + c]       = pk2h(v[0] * s, v[1] * s);
                *(uint32_t*)&C[(size_t)(r + 8) * N + c] = pk2h(v[2] * s, v[3] * s);
            }
        }
}

#define QKV_SMEM (3 * (128 * GASTR * 2 + 32 * 136 * 2))
#define OUT_SMEM (3 * (64 * GASTR * 2 + 32 * 72 * 2))

__global__ __launch_bounds__(256, 2) void gemm_qkv_kernel()
{
    extern __shared__ char gsm[];
    int by = blockIdx.y;
    const __half *A, *Bw; void* C; int mode;
    if (by < 16)      { A = g_QinH; Bw = g_WqH; C = g_Qh; mode = 2; }
    else if (by < 48) { A = g_KvH;  Bw = g_WkH; C = g_Kh; mode = 1; by -= 16; }
    else              { A = g_KvH;  Bw = g_WvH; C = g_Vh; mode = 3; by -= 48; }
    gemm_h_body<128, 128>(A, Bw, C, HID_, DIM_, by * 128, mode, gsm);
}

__global__ __launch_bounds__(256, 3) void gemm_out_kernel(float* __restrict__ out)
{
    extern __shared__ char gsm[];
    gemm_h_body<64, 64>(g_attnh, g_WoH, out, DIM_, HID_, blockIdx.y * 64, 0, gsm);
}

// ---------------------------------------------------------------------------
// fp16 flash attention (R15 structure): CTA split-K(2), no-max softmax,
// register-resident P, clamp-free nearest LUT, 32-key tiles, 3-stage ring,
// one __syncthreads per tile. 64 q x 1024 keys, 128 thr, 4 CTAs/SM.
// ---------------------------------------------------------------------------
#define AKT    32
#define KSTRH  72
#define VSTRH  40
#define KB_    4608
#define EB_    512
#define VB_    5120
#define STGB   (KB_ + EB_ + VB_)          // 10240 per stage
#define OFF_LUT (3 * STGB)                // 30720; 2048 fp32 = 8192 B
#define ATT_SMEM_BYTES (3 * STGB + 8192)  // 38912

__global__ __launch_bounds__(128, 4) void attn_kernel(const float* __restrict__ qc)
{
    extern __shared__ char smc[];
    float* slut = (float*)(smc + OFF_LUT);

    const int b   = blockIdx.z >> 1;
    const int ks_ = blockIdx.z & 1;
    const int h   = blockIdx.y;
    const int q0  = blockIdx.x * 64;
    const int tid = threadIdx.x;
    const int lane = tid & 31;
    const int w    = tid >> 5;
    const int lq   = lane >> 2;
    const int lr   = lane & 3;
    const int kstart = ks_ * (NK / 2);

    {
        const float* lb = g_lut + h * LUT_N;
        for (int i = tid; i < LUT_N; i += 128) slut[i] = lb[i];
    }

    const int k_lane = (lane & 7) * (KSTRH * 2) + (lane >> 3) * 16;
    const int v_lane = (lane & 7) * (VSTRH * 2) + (lane >> 3) * 16;
    const int e_lane = lane * 16;

    uint32_t qa[4][4], qa2[4];
    float qn2s0, qn2s1;
    {
        const float inv_step2 = g_inv_step2;
        const size_t r0 = ((size_t)(b * NQ + q0 + w * 16 + lq)) * HID_ + h * HD_;
        const size_t r1 = r0 + 8 * HID_;
        #pragma unroll
        for (int ks = 0; ks < 4; ks++) {
            qa[ks][0] = *(const uint32_t*)&g_Qh[r0 + ks * 16 + 2 * lr];
            qa[ks][1] = *(const uint32_t*)&g_Qh[r1 + ks * 16 + 2 * lr];
            qa[ks][2] = *(const uint32_t*)&g_Qh[r0 + ks * 16 + 2 * lr + 8];
            qa[ks][3] = *(const uint32_t*)&g_Qh[r1 + ks * 16 + 2 * lr + 8];
        }
        const float* p0 = qc + ((size_t)b * NQ + q0 + w * 16 + lq) * 3;
        const float* p1 = p0 + 8 * 3;
        float c0[4] = {p0[0], p0[1], p0[2], 1.0f};
        float c1[4] = {p1[0], p1[1], p1[2], 1.0f};
        qa2[0] = f2tf(c0[lr]);
        qa2[1] = f2tf(c1[lr]);
        qa2[2] = 0u; qa2[3] = 0u;
        // +LUT_OFF guard folded into accumulator init (clamp-free indexing)
        qn2s0 = fmaf(c0[0], c0[0], fmaf(c0[1], c0[1], c0[2] * c0[2])) * inv_step2
              + (float)LUT_OFF;
        qn2s1 = fmaf(c1[0], c1[0], fmaf(c1[1], c1[1], c1[2] * c1[2])) * inv_step2
              + (float)LUT_OFF;
    }

    float of[8][4] = {};
    float l0 = 0.f, l1 = 0.f;

    const __half* Kp  = g_Kh + ((size_t)b * NK) * HID_ + h * HD_;
    const __half* Vpt = g_Vh + ((size_t)(b * H_ + h) * HD_) * NK;

    const int lkey = tid >> 2;
    const int qo   = (tid & 3) * 16;
    const int vrow = tid >> 1;
    const int vcb  = (tid & 1) * 16;

    auto issue = [&](int t) {
        char* stg = smc + (t % 3) * STGB;
        const __half* kg = Kp + (size_t)(kstart + t * AKT + lkey) * HID_ + qo;
        uint32_t kd = s2u(stg + (lkey * KSTRH + qo) * 2);
        cpa16(kd, kg); cpa16(kd + 16, kg + 8);
        if (tid < AKT)
            cpa16(s2u(stg + KB_ + tid * 16),
                  g_ext + (size_t)b * NK + kstart + t * AKT + tid);
        const __half* vg = Vpt + (size_t)vrow * NK + kstart + t * AKT + vcb;
        uint32_t vd = s2u(stg + KB_ + EB_ + (vrow * VSTRH + vcb) * 2);
        cpa16(vd, vg); cpa16(vd + 16, vg + 8);
        asm volatile("cp.async.commit_group;" ::: "memory");
    };

    const int NT = (NK / 2) / AKT;
    issue(0); issue(1);

    for (int t = 0; t < NT; t++) {
        if (t + 1 < NT) {
            asm volatile("cp.async.wait_group 1;" ::: "memory");
        } else {
            asm volatile("cp.async.wait_group 0;" ::: "memory");
        }
        __syncthreads();
        if (t + 2 < NT) issue(t + 2);

        char* stg = smc + (t % 3) * STGB;
        const uint32_t kb_s = s2u(stg);
        const uint32_t eb_s = s2u(stg + KB_);
        const uint32_t vb_s = s2u(stg + KB_ + EB_);

        // ---- QK^T ----
        float sacc[4][4] = {};
        #pragma unroll
        for (int nf = 0; nf < 4; nf++) {
            const uint32_t kbase = kb_s + nf * 8 * (KSTRH * 2) + k_lane;
            uint32_t kb[4];
            ldsm4(kb, kbase);
            mma16(sacc[nf], qa[0], kb[0], kb[1]);
            mma16(sacc[nf], qa[1], kb[2], kb[3]);
            ldsm4(kb, kbase + 64);
            mma16(sacc[nf], qa[2], kb[0], kb[1]);
            mma16(sacc[nf], qa[3], kb[2], kb[3]);
        }

        // ---- d^2 ext fragments ----
        uint32_t eb[4];
        ldsm4(eb, eb_s + e_lane);

        // ---- bias (clamp-free nearest LUT) + no-max softmax; P -> A-frags ----
        uint32_t pa[2][4];
        float ps0 = 0.f, ps1 = 0.f;
        #pragma unroll
        for (int nf = 0; nf < 4; nf++) {
            float dd4[4] = {qn2s0, qn2s0, qn2s1, qn2s1};
            mma8t(dd4, qa2, eb[nf]);
            float p4[4];
            #pragma unroll
            for (int j = 0; j < 4; j++)
                p4[j] = ex2(sacc[nf][j] + slut[__float2int_rn(dd4[j])]);
            ps0 += p4[0] + p4[1];
            ps1 += p4[2] + p4[3];
            pa[nf >> 1][(nf & 1) * 2]     = pk2h(p4[0], p4[1]);
            pa[nf >> 1][(nf & 1) * 2 + 1] = pk2h(p4[2], p4[3]);
        }
        l0 += ps0;
        l1 += ps1;

        // ---- P V (P in registers, V via LDSM) ----
        #pragma unroll
        for (int nf = 0; nf < 8; nf++) {
            uint32_t vb[4];
            ldsm4(vb, vb_s + nf * 8 * (VSTRH * 2) + v_lane);
            mma16(of[nf], pa[0], vb[0], vb[1]);
            mma16(of[nf], pa[1], vb[2], vb[3]);
        }
    }

    // epilogue: unnormalized fp32 partial + l
    float* pO = ks_ ? g_O2 : g_attn;
    const size_t r0 = ((size_t)(b * NQ + q0 + w * 16 + lq)) * HID_ + h * HD_;
    const size_t r1 = r0 + 8 * HID_;
    #pragma unroll
    for (int nf = 0; nf < 8; nf++) {
        const int c = nf * 8 + 2 * lr;
        *(float2*)&pO[r0 + c] = make_float2(of[nf][0], of[nf][1]);
        *(float2*)&pO[r1 + c] = make_float2(of[nf][2], of[nf][3]);
    }
    l0 += __shfl_xor_sync(0xffffffffu, l0, 1);
    l0 += __shfl_xor_sync(0xffffffffu, l0, 2);
    l1 += __shfl_xor_sync(0xffffffffu, l1, 1);
    l1 += __shfl_xor_sync(0xffffffffu, l1, 2);
    if (lr == 0) {
        const size_t base = (((size_t)ks_ * B_ + b) * H_ + h) * NQ;
        const int qr = q0 + w * 16 + lq;
        g_l[base + qr]     = l0;
        g_l[base + qr + 8] = l1;
    }
}

// ---------------------------------------------------------------------------
__global__ __launch_bounds__(512) void merge_kernel()
{
    const int row = blockIdx.x;
    const int b = row >> 10;
    const int q = row & 1023;
    const int c = threadIdx.x;
    const int h = c >> 6;

    const float lA = g_l[(((size_t)0 * B_ + b) * H_ + h) * NQ + q];
    const float lB = g_l[(((size_t)1 * B_ + b) * H_ + h) * NQ + q];
    const float inv = __fdividef(1.f, lA + lB);

    const size_t o = (size_t)row * HID_ + c;
    g_attnh[o] = __float2half_rn((g_attn[o] + g_O2[o]) * inv);
}

// ---------------------------------------------------------------------------
extern "C" void kernel_launch(void* const* d_in, const int* in_sizes, int n_in,
                              void* d_out, int out_size)
{
    const float* q_in      = (const float*)d_in[0];
    const float* kv_in     = (const float*)d_in[1];
    const float* q_coords  = (const float*)d_in[2];
    const float* kv_coords = (const float*)d_in[3];
    const float* Wq        = (const float*)d_in[4];
    const float* Wk        = (const float*)d_in[5];
    const float* Wv        = (const float*)d_in[6];
    const float* Wo        = (const float*)d_in[7];
    const float* W1        = (const float*)d_in[8];
    const float* b1        = (const float*)d_in[9];
    const float* W2        = (const float*)d_in[10];
    const float* b2        = (const float*)d_in[11];
    float* out             = (float*)d_out;

    static bool attr_set = false;
    if (!attr_set) {
        cudaFuncSetAttribute(attn_kernel,
            cudaFuncAttributeMaxDynamicSharedMemorySize, ATT_SMEM_BYTES);
        cudaFuncSetAttribute(gemm_qkv_kernel,
            cudaFuncAttributeMaxDynamicSharedMemorySize, QKV_SMEM);
        cudaFuncSetAttribute(gemm_out_kernel,
            cudaFuncAttributeMaxDynamicSharedMemorySize, OUT_SMEM);
        attr_set = true;
    }

    conv_kernel<<<4096, 256>>>((const float4*)q_in, (const float4*)kv_in,
                               (const float4*)Wq, (const float4*)Wk,
                               (const float4*)Wv, (const float4*)Wo,
                               q_coords, kv_coords);
    lut_kernel<<<24, 256>>>(W1, b1, W2, b2, kv_coords);

    gemm_qkv_kernel<<<dim3(HID_ / 128, 80), 256, QKV_SMEM>>>();

    attn_kernel<<<dim3(NQ / 64, H_, B_ * 2), 128, ATT_SMEM_BYTES>>>(q_coords);

    merge_kernel<<<B_ * NQ, 512>>>();

    gemm_out_kernel<<<dim3(DIM_ / 64, (B_ * NQ) / 64), 256, OUT_SMEM>>>(out);
}